// round 14
// baseline (speedup 1.0000x reference)
#include <cuda_runtime.h>
#include <cuda_bf16.h>
#include <cuda_fp16.h>
#include <cstdint>

#define HD   128
#define NMAX 100000
#define EMAX 1700000
#define EPS  1e-5f

typedef unsigned long long ull;

// ---------------- scratch (__device__ globals; no runtime allocation) ----------
__device__ int    g_deg [6 * NMAX];                     // [out0,in0,out1,in1,out2,in2]
__device__ int    g_off [3 * (NMAX + 1)];
__device__ int    g_cur [3 * NMAX];
__device__ int    g_csum[3 * 512];
__device__ int2   g_csr [3 * (size_t)EMAX];             // (src, bits(rs_out[src]))
__device__ __half g_af  [(size_t)3 * NMAX * HD];        // agg (fp16)
__device__ __half g_wt  [2 * 4 * HD * HD];              // [layer][slot0..3][k][n] fp16
__device__ __half g_xh  [(size_t)NMAX * HD];            // fp16 copy of x
__device__ __half g_h   [(size_t)NMAX * HD];            // layer-0 output (fp16)

// ---------------- mma.sync / ldmatrix helpers (portable sm_80+ PTX) -------------
__device__ __forceinline__ uint32_t smem_to_u32(const void* p) {
    uint32_t a;
    asm("{ .reg .u64 t; cvta.to.shared.u64 t, %1; cvt.u32.u64 %0, t; }" : "=r"(a) : "l"(p));
    return a;
}
__device__ __forceinline__ void ldsm_x4(uint32_t r[4], uint32_t addr) {
    asm volatile("ldmatrix.sync.aligned.m8n8.x4.shared.b16 {%0,%1,%2,%3}, [%4];"
                 : "=r"(r[0]), "=r"(r[1]), "=r"(r[2]), "=r"(r[3]) : "r"(addr));
}
__device__ __forceinline__ void ldsm_x4t(uint32_t r[4], uint32_t addr) {
    asm volatile("ldmatrix.sync.aligned.m8n8.x4.trans.shared.b16 {%0,%1,%2,%3}, [%4];"
                 : "=r"(r[0]), "=r"(r[1]), "=r"(r[2]), "=r"(r[3]) : "r"(addr));
}
__device__ __forceinline__ void mma_f16(float c[4], const uint32_t a[4], uint32_t b0, uint32_t b1) {
    asm volatile("mma.sync.aligned.m16n8k16.row.col.f32.f16.f16.f32 "
                 "{%0,%1,%2,%3}, {%4,%5,%6,%7}, {%8,%9}, {%0,%1,%2,%3};"
                 : "+f"(c[0]), "+f"(c[1]), "+f"(c[2]), "+f"(c[3])
                 : "r"(a[0]), "r"(a[1]), "r"(a[2]), "r"(a[3]), "r"(b0), "r"(b1));
}

// ---------------- fused util: zero deg, x -> fp16, weight prep ------------------
__global__ void prework_util_kernel(int* __restrict__ deg,
                                    const float* __restrict__ x, __half* __restrict__ xh,
                                    const float* __restrict__ Wg0, const float* __restrict__ Wg1,
                                    const float* __restrict__ Wfc, __half* __restrict__ wt,
                                    int n, int c4, int zb, int xb) {
    int b = blockIdx.x;
    if (b < zb) {
        int i = b * 256 + threadIdx.x;
        if (i < 6 * n) deg[i] = 0;
    } else if (b < zb + xb) {
        int i = (b - zb) * 256 + threadIdx.x;
        if (i < c4) {
            float4 v = __ldg((const float4*)x + i);
            __half2 p0 = __floats2half2_rn(v.x, v.y);
            __half2 p1 = __floats2half2_rn(v.z, v.w);
            uint2 o = make_uint2(*(uint32_t*)&p0, *(uint32_t*)&p1);
            ((uint2*)xh)[i] = o;
        }
    } else {
        int idx = (b - zb - xb) * 256 + threadIdx.x;
        if (idx < 2 * 4 * 16384) {
            int kn = idx & 16383;
            int slot = (idx >> 14) & 3;
            int layer = idx >> 16;
            float v;
            if (slot < 3) v = (layer ? Wg1 : Wg0)[(size_t)slot * 16384 + kn];
            else          v = Wfc[(size_t)layer * 16384 + kn];
            wt[(size_t)(layer * 4 + slot) * 16384 + kn] = __float2half_rn(v);
        }
    }
}

// merged over 3 relations via blockIdx.y (measured win: 51us vs 3x21us)
__global__ void count_pair3_kernel(const int* __restrict__ s0, const int* __restrict__ d0,
                                   const int* __restrict__ s1, const int* __restrict__ d1,
                                   const int* __restrict__ s2, const int* __restrict__ d2,
                                   int e0, int e1, int e2,
                                   int* __restrict__ deg, int n) {
    int r = blockIdx.y;
    const int* src = (r == 0) ? s0 : (r == 1) ? s1 : s2;
    const int* dst = (r == 0) ? d0 : (r == 1) ? d1 : d2;
    int e = (r == 0) ? e0 : (r == 1) ? e1 : e2;
    int i = blockIdx.x * blockDim.x + threadIdx.x;
    if (i >= e) return;
    atomicAdd(deg + (size_t)2 * r * n + src[i], 1);
    atomicAdd(deg + (size_t)(2 * r + 1) * n + dst[i], 1);
}

// ---------------- CSR build (parallel 3-kernel scan, per relation) --------------
__global__ void chunk_sum_kernel(const int* __restrict__ deg, int* __restrict__ csum, int n) {
    __shared__ int s[256];
    int i = blockIdx.x * 256 + threadIdx.x;
    s[threadIdx.x] = (i < n) ? deg[i] : 0;
    __syncthreads();
    #pragma unroll
    for (int st = 128; st > 0; st >>= 1) {
        if (threadIdx.x < st) s[threadIdx.x] += s[threadIdx.x + st];
        __syncthreads();
    }
    if (threadIdx.x == 0) csum[blockIdx.x] = s[0];
}

__global__ void scan_chunks_kernel(int* __restrict__ csum, int nc) {
    __shared__ int s[512];
    int t = threadIdx.x;
    int v0 = (t < nc) ? csum[t] : 0;
    s[t] = v0;
    __syncthreads();
    #pragma unroll
    for (int off = 1; off < 512; off <<= 1) {
        int v = (t >= off) ? s[t - off] : 0;
        __syncthreads();
        s[t] += v;
        __syncthreads();
    }
    if (t < nc) csum[t] = s[t] - v0;
}

__global__ void write_offsets_kernel(const int* __restrict__ deg, const int* __restrict__ csum,
                                     int* __restrict__ off, int* __restrict__ cur, int n) {
    __shared__ int s[256];
    int t = threadIdx.x;
    int i = blockIdx.x * 256 + t;
    int d = (i < n) ? deg[i] : 0;
    s[t] = d;
    __syncthreads();
    #pragma unroll
    for (int o = 1; o < 256; o <<= 1) {
        int v = (t >= o) ? s[t - o] : 0;
        __syncthreads();
        s[t] += v;
        __syncthreads();
    }
    int excl = s[t] - d + csum[blockIdx.x];
    if (i < n) {
        off[i] = excl;
        cur[i] = excl;
        if (i == n - 1) off[n] = excl + d;
    }
}

// rs_out folded: compute rsqrt from deg_out directly
__global__ void csr_fill_kernel(const int* __restrict__ src, const int* __restrict__ dst,
                                const int* __restrict__ deg_out,
                                int* __restrict__ cur, int2* __restrict__ csr, int e) {
    int i = blockIdx.x * blockDim.x + threadIdx.x;
    if (i >= e) return;
    int s = src[i];
    int d = __ldg(deg_out + s);
    float c = rsqrtf((float)(d < 1 ? 1 : d));
    int slot = atomicAdd(cur + dst[i], 1);
    csr[slot] = make_int2(s, __float_as_int(c));
}

// ---------------- gather, flat-1D merged over 3 relations -----------------------
// global warp id in [0, 3n): r = wg / n, w = wg - r*n. Preserves the block
// ordering of 3 sequential launches (relation 0 first) without launch gaps.
__global__ void gather_all_kernel(const __half* __restrict__ h,
                                  const int2* __restrict__ csrb, const int* __restrict__ offb,
                                  const int* __restrict__ deg, // g_deg base
                                  __half* __restrict__ afb, int n) {
    int wg   = (blockIdx.x * blockDim.x + threadIdx.x) >> 5;
    int lane = threadIdx.x & 31;
    if (wg >= 3 * n) return;
    int r = wg / n;
    int w = wg - r * n;
    const int2* csr = csrb + (size_t)r * EMAX;
    const int* off  = offb + (size_t)r * (NMAX + 1);
    __half* af      = afb + (size_t)r * n * HD;

    int e0 = __ldg(off + w), e1 = __ldg(off + w + 1);
    float4 acc = make_float4(0.f, 0.f, 0.f, 0.f);
    int e = e0;
    for (; e + 1 < e1; e += 2) {
        int2 ea = __ldg(csr + e), eb = __ldg(csr + e + 1);
        float ca = __int_as_float(ea.y), cb = __int_as_float(eb.y);
        uint2 ra = __ldg((const uint2*)(h + (size_t)ea.x * HD) + lane);
        uint2 rb = __ldg((const uint2*)(h + (size_t)eb.x * HD) + lane);
        float2 a0 = __half22float2(*(__half2*)&ra.x), a1 = __half22float2(*(__half2*)&ra.y);
        float2 b0 = __half22float2(*(__half2*)&rb.x), b1 = __half22float2(*(__half2*)&rb.y);
        acc.x = fmaf(a0.x, ca, acc.x); acc.y = fmaf(a0.y, ca, acc.y);
        acc.z = fmaf(a1.x, ca, acc.z); acc.w = fmaf(a1.y, ca, acc.w);
        acc.x = fmaf(b0.x, cb, acc.x); acc.y = fmaf(b0.y, cb, acc.y);
        acc.z = fmaf(b1.x, cb, acc.z); acc.w = fmaf(b1.y, cb, acc.w);
    }
    if (e < e1) {
        int2 ea = __ldg(csr + e);
        float ca = __int_as_float(ea.y);
        uint2 ra = __ldg((const uint2*)(h + (size_t)ea.x * HD) + lane);
        float2 a0 = __half22float2(*(__half2*)&ra.x), a1 = __half22float2(*(__half2*)&ra.y);
        acc.x = fmaf(a0.x, ca, acc.x); acc.y = fmaf(a0.y, ca, acc.y);
        acc.z = fmaf(a1.x, ca, acc.z); acc.w = fmaf(a1.y, ca, acc.w);
    }
    int din = __ldg(deg + (size_t)(2 * r + 1) * n + w);
    float ri = rsqrtf((float)(din < 1 ? 1 : din));
    __half2 p0 = __floats2half2_rn(acc.x * ri, acc.y * ri);
    __half2 p1 = __floats2half2_rn(acc.z * ri, acc.w * ri);
    uint2 hv = make_uint2(*(uint32_t*)&p0, *(uint32_t*)&p1);
    ((uint2*)(af + (size_t)w * HD))[lane] = hv;
}

// ---------------- fused mma.sync layer kernel (single-pass fp16) ----------------
// Block = 128 nodes x 128 outputs, 256 threads (8 warps, 4m x 2n, warp tile 32x64).

#define SA_STR 40      // phase-1 A row stride (fp16): 128x40
#define SB_STR 136     // B row stride (fp16): 32x136
#define TB_STR 136     // tbuf row stride (fp16): 128x136

#define OFF_BGS  0                                  // 128 f32
#define OFF_BFC  512
#define OFF_SC   1024
#define OFF_SH   1536
#define OFF_SB   2048                               // B (8704)
#define OFF_TBUF (OFF_SB + 32 * SB_STR * 2)         // t (34816); phase-1 A overlays
#define OFF_SA   OFF_TBUF
#define SMEM_TOT (OFF_TBUF + 128 * TB_STR * 2)      // 45568 B

__global__ __launch_bounds__(256) void mma_layer_kernel(
    const __half* __restrict__ af,     // [3n][HD]
    const __half* __restrict__ wt,     // this layer: [4 slots][128][128]
    const float* __restrict__ bg,      // [3][HD]
    const float* __restrict__ bfc,
    const float* __restrict__ gamma, const float* __restrict__ beta,
    const float* __restrict__ mean,  const float* __restrict__ var,
    float* __restrict__ outf,          // fp32 output (layer 1) or null
    __half* __restrict__ outh,         // fp16 output (layer 0) or null
    int n)
{
    extern __shared__ char smem[];
    const uint32_t sb = smem_to_u32(smem);
    float* bgs  = (float*)(smem + OFF_BGS);
    float* bfcs = (float*)(smem + OFF_BFC);
    float* scs  = (float*)(smem + OFF_SC);
    float* shs  = (float*)(smem + OFF_SH);

    const int tid  = threadIdx.x;
    const int lane = tid & 31;
    const int wid  = tid >> 5;
    const int wm   = wid & 3;          // warp row  (m: 32 each)
    const int wn   = wid >> 2;         // warp col  (n: 64 each)
    const int bn0  = blockIdx.x * 128;

    if (tid < HD) {
        bgs[tid]  = __ldg(bg + tid) + __ldg(bg + HD + tid) + __ldg(bg + 2 * HD + tid);
        bfcs[tid] = __ldg(bfc + tid);
        float sc = __ldg(gamma + tid) * rsqrtf(__ldg(var + tid) + EPS);
        scs[tid] = sc;
        shs[tid] = __ldg(beta + tid) - __ldg(mean + tid) * sc;
    }

    const int lrow = lane & 15, lcol = lane >> 4;

    float acc[2][8][4];
    #pragma unroll
    for (int mi = 0; mi < 2; mi++)
        #pragma unroll
        for (int t = 0; t < 8; t++)
            #pragma unroll
            for (int q = 0; q < 4; q++) acc[mi][t][q] = 0.f;

    const int ar = tid >> 1, ahalf = tid & 1;        // A: 128 rows x 2 halves of 16
    const int br = tid >> 3, bc = tid & 7;           // B: 32 rows x 8 chunks of 16

    // ================= phase 1: 3 relations, K=128 each =======================
    for (int r = 0; r < 3; r++) {
        const __half* af_base = af + (size_t)r * n * HD;
        const __half* wp_base = wt + (size_t)r * 16384;
        for (int kc = 0; kc < 4; kc++) {
            __syncthreads();
            // stage A [128][32]
            {
                int gnode = bn0 + ar;
                uint4 v0 = {0,0,0,0}, v1 = {0,0,0,0};
                if (gnode < n) {
                    const uint4* ph = (const uint4*)(af_base + (size_t)gnode * HD + kc * 32 + ahalf * 16);
                    v0 = __ldg(ph); v1 = __ldg(ph + 1);
                }
                __half* dh = (__half*)(smem + OFF_SA) + ar * SA_STR + ahalf * 16;
                *(uint4*)dh = v0; *(uint4*)(dh + 8) = v1;
            }
            // stage B [32][128]
            {
                const uint4* ph = (const uint4*)(wp_base + (size_t)(kc * 32 + br) * HD + bc * 16);
                uint4 v0 = __ldg(ph), v1 = __ldg(ph + 1);
                __half* dh = (__half*)(smem + OFF_SB) + br * SB_STR + bc * 16;
                *(uint4*)dh = v0; *(uint4*)(dh + 8) = v1;
            }
            __syncthreads();

            #pragma unroll
            for (int kb = 0; kb < 32; kb += 16) {
                uint32_t ahf[2][4];
                #pragma unroll
                for (int mi = 0; mi < 2; mi++) {
                    uint32_t aoff = (uint32_t)((wm * 32 + mi * 16 + lrow) * SA_STR + kb + lcol * 8) * 2;
                    ldsm_x4(ahf[mi], sb + OFF_SA + aoff);
                }
                #pragma unroll
                for (int g = 0; g < 4; g++) {
                    uint32_t bh[4];
                    uint32_t boff = (uint32_t)((kb + lrow) * SB_STR + wn * 64 + g * 16 + lcol * 8) * 2;
                    ldsm_x4t(bh, sb + OFF_SB + boff);
                    #pragma unroll
                    for (int mi = 0; mi < 2; mi++) {
                        #pragma unroll
                        for (int nj = 0; nj < 2; nj++)
                            mma_f16(acc[mi][g * 2 + nj], ahf[mi], bh[nj * 2], bh[nj * 2 + 1]);
                    }
                }
            }
        }
    }

    // ================= transition: t = acc + bg -> tbuf (fp16) =================
    __syncthreads();
    {
        __half* th = (__half*)(smem + OFF_TBUF);
        #pragma unroll
        for (int mi = 0; mi < 2; mi++) {
            #pragma unroll
            for (int t = 0; t < 8; t++) {
                int g = t >> 1, nj = t & 1;
                int row0 = wm * 32 + mi * 16 + (lane >> 2);
                int col  = wn * 64 + g * 16 + nj * 8 + (lane & 3) * 2;
                float b0 = bgs[col], b1 = bgs[col + 1];
                #pragma unroll
                for (int half = 0; half < 2; half++) {
                    int row = row0 + half * 8;
                    __half2 hp = __floats2half2_rn(acc[mi][t][half * 2] + b0,
                                                   acc[mi][t][half * 2 + 1] + b1);
                    *(uint32_t*)(th + row * TB_STR + col) = *(uint32_t*)&hp;
                }
                #pragma unroll
                for (int q = 0; q < 4; q++) acc[mi][t][q] = 0.f;
            }
        }
    }

    // ================= phase 2: y = t @ Wfc =====================================
    {
        const __half* wp_base = wt + (size_t)3 * 16384;
        for (int kc = 0; kc < 4; kc++) {
            __syncthreads();
            {
                const uint4* ph = (const uint4*)(wp_base + (size_t)(kc * 32 + br) * HD + bc * 16);
                uint4 v0 = __ldg(ph), v1 = __ldg(ph + 1);
                __half* dh = (__half*)(smem + OFF_SB) + br * SB_STR + bc * 16;
                *(uint4*)dh = v0; *(uint4*)(dh + 8) = v1;
            }
            __syncthreads();

            #pragma unroll
            for (int kb2 = 0; kb2 < 32; kb2 += 16) {
                int kb = kc * 32 + kb2;
                uint32_t ahf[2][4];
                #pragma unroll
                for (int mi = 0; mi < 2; mi++) {
                    uint32_t aoff = (uint32_t)((wm * 32 + mi * 16 + lrow) * TB_STR + kb + lcol * 8) * 2;
                    ldsm_x4(ahf[mi], sb + OFF_TBUF + aoff);
                }
                #pragma unroll
                for (int g = 0; g < 4; g++) {
                    uint32_t bh[4];
                    uint32_t boff = (uint32_t)((kb2 + lrow) * SB_STR + wn * 64 + g * 16 + lcol * 8) * 2;
                    ldsm_x4t(bh, sb + OFF_SB + boff);
                    #pragma unroll
                    for (int mi = 0; mi < 2; mi++) {
                        #pragma unroll
                        for (int nj = 0; nj < 2; nj++)
                            mma_f16(acc[mi][g * 2 + nj], ahf[mi], bh[nj * 2], bh[nj * 2 + 1]);
                    }
                }
            }
        }
    }

    // ================= epilogue: ReLU + BN, store ==============================
    #pragma unroll
    for (int mi = 0; mi < 2; mi++) {
        #pragma unroll
        for (int t = 0; t < 8; t++) {
            int g = t >> 1, nj = t & 1;
            int row0 = wm * 32 + mi * 16 + (lane >> 2);
            int col  = wn * 64 + g * 16 + nj * 8 + (lane & 3) * 2;
            float bf0 = bfcs[col], bf1 = bfcs[col + 1];
            float sc0 = scs[col], sc1 = scs[col + 1];
            float sh0 = shs[col], sh1 = shs[col + 1];
            #pragma unroll
            for (int half = 0; half < 2; half++) {
                int node = bn0 + row0 + half * 8;
                if (node < n) {
                    float y0 = fmaxf(acc[mi][t][half * 2]     + bf0, 0.f);
                    float y1 = fmaxf(acc[mi][t][half * 2 + 1] + bf1, 0.f);
                    float v0 = y0 * sc0 + sh0;
                    float v1 = y1 * sc1 + sh1;
                    if (outh) {
                        __half2 hv = __floats2half2_rn(v0, v1);
                        *(uint32_t*)(outh + (size_t)node * HD + col) = *(uint32_t*)&hv;
                    } else {
                        *(float2*)(outf + (size_t)node * HD + col) = make_float2(v0, v1);
                    }
                }
            }
        }
    }
}

// ---------------- launch --------------------------------------------------------
extern "C" void kernel_launch(void* const* d_in, const int* in_sizes, int n_in,
                              void* d_out, int out_size)
{
    const float* x     = (const float*)d_in[0];
    const int* srcs[3] = {(const int*)d_in[1], (const int*)d_in[3], (const int*)d_in[5]};
    const int* dsts[3] = {(const int*)d_in[2], (const int*)d_in[4], (const int*)d_in[6]};
    const float* Wg0   = (const float*)d_in[7];
    const float* bg0   = (const float*)d_in[8];
    const float* Wg1   = (const float*)d_in[9];
    const float* bg1   = (const float*)d_in[10];
    const float* Wfc   = (const float*)d_in[11];
    const float* bfc   = (const float*)d_in[12];
    const float* gamma = (const float*)d_in[13];
    const float* beta  = (const float*)d_in[14];
    const float* mean  = (const float*)d_in[15];
    const float* var   = (const float*)d_in[16];

    int n = in_sizes[0] / HD;
    int es[3] = {in_sizes[1], in_sizes[3], in_sizes[5]};
    int emax = es[0] > es[1] ? es[0] : es[1];
    if (es[2] > emax) emax = es[2];

    int *p_deg, *p_off, *p_cur, *p_csum;
    int2* p_csr;
    __half *p_af, *p_wt, *p_xh, *p_h;
    cudaGetSymbolAddress((void**)&p_deg,  g_deg);
    cudaGetSymbolAddress((void**)&p_off,  g_off);
    cudaGetSymbolAddress((void**)&p_cur,  g_cur);
    cudaGetSymbolAddress((void**)&p_csum, g_csum);
    cudaGetSymbolAddress((void**)&p_csr,  g_csr);
    cudaGetSymbolAddress((void**)&p_af,   g_af);
    cudaGetSymbolAddress((void**)&p_wt,   g_wt);
    cudaGetSymbolAddress((void**)&p_xh,   g_xh);
    cudaGetSymbolAddress((void**)&p_h,    g_h);

    const int NT = 256;
    const int nchunks = (n + 255) / 256;

    cudaFuncSetAttribute(mma_layer_kernel, cudaFuncAttributeMaxDynamicSharedMemorySize, SMEM_TOT);

    // 0) fused util: zero deg, x->fp16, weight prep (1 launch)
    int c4 = n * HD / 4;
    int zb = (6 * n + 255) / 256;
    int xb = (c4 + 255) / 256;
    int ub = zb + xb + 512;
    prework_util_kernel<<<ub, 256>>>(p_deg, x, p_xh, Wg0, Wg1, Wfc, p_wt, n, c4, zb, xb);

    // 1) degrees (merged over relations); rsqrt folded into consumers
    {
        dim3 grid((emax + NT - 1) / NT, 3);
        count_pair3_kernel<<<grid, NT>>>(srcs[0], dsts[0], srcs[1], dsts[1], srcs[2], dsts[2],
                                         es[0], es[1], es[2], p_deg, n);
    }

    // 2) CSR by dst (parallel 3-kernel scan, per relation)
    for (int r = 0; r < 3; r++) {
        const int* deg_in  = p_deg + (size_t)(2 * r + 1) * n;
        const int* deg_out = p_deg + (size_t)2 * r * n;
        int* off  = p_off  + (size_t)r * (NMAX + 1);
        int* cur  = p_cur  + (size_t)r * NMAX;
        int* csum = p_csum + (size_t)r * 512;
        int2* csr = p_csr  + (size_t)r * EMAX;
        chunk_sum_kernel<<<nchunks, 256>>>(deg_in, csum, n);
        scan_chunks_kernel<<<1, 512>>>(csum, nchunks);
        write_offsets_kernel<<<nchunks, 256>>>(deg_in, csum, off, cur, n);
        csr_fill_kernel<<<(es[r] + NT - 1) / NT, NT>>>(
            srcs[r], dsts[r], deg_out, cur, csr, es[r]);
    }

    // 3) layers (single flat gather launch per layer)
    int mblocks = (n + 127) / 128;
    for (int layer = 0; layer < 2; layer++) {
        const __half* hin = (layer == 0) ? p_xh : p_h;
        long long thr = (long long)3 * n * 32;
        int gblocks = (int)((thr + NT - 1) / NT);
        gather_all_kernel<<<gblocks, NT>>>(hin, p_csr, p_off, p_deg, p_af, n);
        mma_layer_kernel<<<mblocks, 256, SMEM_TOT>>>(
            p_af,
            p_wt + (size_t)layer * 4 * 16384,
            (layer == 0) ? bg0 : bg1,
            bfc + (size_t)layer * HD,
            gamma + (size_t)layer * HD, beta + (size_t)layer * HD,
            mean + (size_t)layer * HD, var + (size_t)layer * HD,
            (layer == 0) ? nullptr : (float*)d_out,
            (layer == 0) ? p_h : nullptr,
            n);
    }
}

// round 15
// speedup vs baseline: 1.0315x; 1.0315x over previous
#include <cuda_runtime.h>
#include <cuda_bf16.h>
#include <cuda_fp16.h>
#include <cstdint>

#define HD   128
#define NMAX 100000
#define EMAX 1700000
#define EPS  1e-5f

typedef unsigned long long ull;

// ---------------- scratch (__device__ globals; no runtime allocation) ----------
__device__ int    g_deg [6 * NMAX];                     // [out0,in0,out1,in1,out2,in2]
__device__ int    g_off [3 * (NMAX + 1)];
__device__ int    g_cur [3 * NMAX];
__device__ int    g_csum[3 * 512];
__device__ int2   g_csr [3 * (size_t)EMAX];             // (src, bits(rs_out[src]))
__device__ __half g_af  [(size_t)3 * NMAX * HD];        // agg (fp16)
__device__ __half g_wt  [2 * 4 * HD * HD];              // [layer][slot0..3][k][n] fp16
__device__ __half g_xh  [(size_t)NMAX * HD];            // fp16 copy of x
__device__ __half g_h   [(size_t)NMAX * HD];            // layer-0 output (fp16)

// ---------------- mma.sync / ldmatrix helpers (portable sm_80+ PTX) -------------
__device__ __forceinline__ uint32_t smem_to_u32(const void* p) {
    uint32_t a;
    asm("{ .reg .u64 t; cvta.to.shared.u64 t, %1; cvt.u32.u64 %0, t; }" : "=r"(a) : "l"(p));
    return a;
}
__device__ __forceinline__ void ldsm_x4(uint32_t r[4], uint32_t addr) {
    asm volatile("ldmatrix.sync.aligned.m8n8.x4.shared.b16 {%0,%1,%2,%3}, [%4];"
                 : "=r"(r[0]), "=r"(r[1]), "=r"(r[2]), "=r"(r[3]) : "r"(addr));
}
__device__ __forceinline__ void ldsm_x4t(uint32_t r[4], uint32_t addr) {
    asm volatile("ldmatrix.sync.aligned.m8n8.x4.trans.shared.b16 {%0,%1,%2,%3}, [%4];"
                 : "=r"(r[0]), "=r"(r[1]), "=r"(r[2]), "=r"(r[3]) : "r"(addr));
}
__device__ __forceinline__ void mma_f16(float c[4], const uint32_t a[4], uint32_t b0, uint32_t b1) {
    asm volatile("mma.sync.aligned.m16n8k16.row.col.f32.f16.f16.f32 "
                 "{%0,%1,%2,%3}, {%4,%5,%6,%7}, {%8,%9}, {%0,%1,%2,%3};"
                 : "+f"(c[0]), "+f"(c[1]), "+f"(c[2]), "+f"(c[3])
                 : "r"(a[0]), "r"(a[1]), "r"(a[2]), "r"(a[3]), "r"(b0), "r"(b1));
}

// ---------------- fused util: zero deg, x -> fp16, weight prep ------------------
__global__ void prework_util_kernel(int* __restrict__ deg,
                                    const float* __restrict__ x, __half* __restrict__ xh,
                                    const float* __restrict__ Wg0, const float* __restrict__ Wg1,
                                    const float* __restrict__ Wfc, __half* __restrict__ wt,
                                    int n, int c4, int zb, int xb) {
    int b = blockIdx.x;
    if (b < zb) {
        int i = b * 256 + threadIdx.x;
        if (i < 6 * n) deg[i] = 0;
    } else if (b < zb + xb) {
        int i = (b - zb) * 256 + threadIdx.x;
        if (i < c4) {
            float4 v = __ldg((const float4*)x + i);
            __half2 p0 = __floats2half2_rn(v.x, v.y);
            __half2 p1 = __floats2half2_rn(v.z, v.w);
            uint2 o = make_uint2(*(uint32_t*)&p0, *(uint32_t*)&p1);
            ((uint2*)xh)[i] = o;
        }
    } else {
        int idx = (b - zb - xb) * 256 + threadIdx.x;
        if (idx < 2 * 4 * 16384) {
            int kn = idx & 16383;
            int slot = (idx >> 14) & 3;
            int layer = idx >> 16;
            float v;
            if (slot < 3) v = (layer ? Wg1 : Wg0)[(size_t)slot * 16384 + kn];
            else          v = Wfc[(size_t)layer * 16384 + kn];
            wt[(size_t)(layer * 4 + slot) * 16384 + kn] = __float2half_rn(v);
        }
    }
}

// merged over 3 relations via blockIdx.y (measured win: 51us vs 3x21us)
__global__ void count_pair3_kernel(const int* __restrict__ s0, const int* __restrict__ d0,
                                   const int* __restrict__ s1, const int* __restrict__ d1,
                                   const int* __restrict__ s2, const int* __restrict__ d2,
                                   int e0, int e1, int e2,
                                   int* __restrict__ deg, int n) {
    int r = blockIdx.y;
    const int* src = (r == 0) ? s0 : (r == 1) ? s1 : s2;
    const int* dst = (r == 0) ? d0 : (r == 1) ? d1 : d2;
    int e = (r == 0) ? e0 : (r == 1) ? e1 : e2;
    int i = blockIdx.x * blockDim.x + threadIdx.x;
    if (i >= e) return;
    atomicAdd(deg + (size_t)2 * r * n + src[i], 1);
    atomicAdd(deg + (size_t)(2 * r + 1) * n + dst[i], 1);
}

// ---------------- CSR build (parallel 3-kernel scan, per relation) --------------
__global__ void chunk_sum_kernel(const int* __restrict__ deg, int* __restrict__ csum, int n) {
    __shared__ int s[256];
    int i = blockIdx.x * 256 + threadIdx.x;
    s[threadIdx.x] = (i < n) ? deg[i] : 0;
    __syncthreads();
    #pragma unroll
    for (int st = 128; st > 0; st >>= 1) {
        if (threadIdx.x < st) s[threadIdx.x] += s[threadIdx.x + st];
        __syncthreads();
    }
    if (threadIdx.x == 0) csum[blockIdx.x] = s[0];
}

__global__ void scan_chunks_kernel(int* __restrict__ csum, int nc) {
    __shared__ int s[512];
    int t = threadIdx.x;
    int v0 = (t < nc) ? csum[t] : 0;
    s[t] = v0;
    __syncthreads();
    #pragma unroll
    for (int off = 1; off < 512; off <<= 1) {
        int v = (t >= off) ? s[t - off] : 0;
        __syncthreads();
        s[t] += v;
        __syncthreads();
    }
    if (t < nc) csum[t] = s[t] - v0;
}

__global__ void write_offsets_kernel(const int* __restrict__ deg, const int* __restrict__ csum,
                                     int* __restrict__ off, int* __restrict__ cur, int n) {
    __shared__ int s[256];
    int t = threadIdx.x;
    int i = blockIdx.x * 256 + t;
    int d = (i < n) ? deg[i] : 0;
    s[t] = d;
    __syncthreads();
    #pragma unroll
    for (int o = 1; o < 256; o <<= 1) {
        int v = (t >= o) ? s[t - o] : 0;
        __syncthreads();
        s[t] += v;
        __syncthreads();
    }
    int excl = s[t] - d + csum[blockIdx.x];
    if (i < n) {
        off[i] = excl;
        cur[i] = excl;
        if (i == n - 1) off[n] = excl + d;
    }
}

// rs_out folded: compute rsqrt from deg_out directly
__global__ void csr_fill_kernel(const int* __restrict__ src, const int* __restrict__ dst,
                                const int* __restrict__ deg_out,
                                int* __restrict__ cur, int2* __restrict__ csr, int e) {
    int i = blockIdx.x * blockDim.x + threadIdx.x;
    if (i >= e) return;
    int s = src[i];
    int d = __ldg(deg_out + s);
    float c = rsqrtf((float)(d < 1 ? 1 : d));
    int slot = atomicAdd(cur + dst[i], 1);
    csr[slot] = make_int2(s, __float_as_int(c));
}

// ---------------- gather (per relation): agg[d] = rs_in[d] * sum rs_out[s] h[s] -
__global__ void gather_kernel(const __half* __restrict__ h,
                              const int2* __restrict__ csr, const int* __restrict__ off,
                              const int* __restrict__ deg_in,
                              __half* __restrict__ af, int n) {
    int w    = (blockIdx.x * blockDim.x + threadIdx.x) >> 5;
    int lane = threadIdx.x & 31;
    if (w >= n) return;
    int e0 = __ldg(off + w), e1 = __ldg(off + w + 1);
    float4 acc = make_float4(0.f, 0.f, 0.f, 0.f);
    int e = e0;
    for (; e + 1 < e1; e += 2) {
        int2 ea = __ldg(csr + e), eb = __ldg(csr + e + 1);
        float ca = __int_as_float(ea.y), cb = __int_as_float(eb.y);
        uint2 ra = __ldg((const uint2*)(h + (size_t)ea.x * HD) + lane);
        uint2 rb = __ldg((const uint2*)(h + (size_t)eb.x * HD) + lane);
        float2 a0 = __half22float2(*(__half2*)&ra.x), a1 = __half22float2(*(__half2*)&ra.y);
        float2 b0 = __half22float2(*(__half2*)&rb.x), b1 = __half22float2(*(__half2*)&rb.y);
        acc.x = fmaf(a0.x, ca, acc.x); acc.y = fmaf(a0.y, ca, acc.y);
        acc.z = fmaf(a1.x, ca, acc.z); acc.w = fmaf(a1.y, ca, acc.w);
        acc.x = fmaf(b0.x, cb, acc.x); acc.y = fmaf(b0.y, cb, acc.y);
        acc.z = fmaf(b1.x, cb, acc.z); acc.w = fmaf(b1.y, cb, acc.w);
    }
    if (e < e1) {
        int2 ea = __ldg(csr + e);
        float ca = __int_as_float(ea.y);
        uint2 ra = __ldg((const uint2*)(h + (size_t)ea.x * HD) + lane);
        float2 a0 = __half22float2(*(__half2*)&ra.x), a1 = __half22float2(*(__half2*)&ra.y);
        acc.x = fmaf(a0.x, ca, acc.x); acc.y = fmaf(a0.y, ca, acc.y);
        acc.z = fmaf(a1.x, ca, acc.z); acc.w = fmaf(a1.y, ca, acc.w);
    }
    int din = __ldg(deg_in + w);
    float ri = rsqrtf((float)(din < 1 ? 1 : din));
    __half2 p0 = __floats2half2_rn(acc.x * ri, acc.y * ri);
    __half2 p1 = __floats2half2_rn(acc.z * ri, acc.w * ri);
    uint2 hv = make_uint2(*(uint32_t*)&p0, *(uint32_t*)&p1);
    ((uint2*)(af + (size_t)w * HD))[lane] = hv;
}

// ---------------- fused mma.sync layer kernel (single-pass fp16) ----------------
// Block = 128 nodes x 128 outputs, 256 threads (8 warps, 4m x 2n, warp tile 32x64).

#define SA_STR 40      // phase-1 A row stride (fp16): 128x40
#define SB_STR 136     // B row stride (fp16): 32x136
#define TB_STR 136     // tbuf row stride (fp16): 128x136

#define OFF_BGS  0                                  // 128 f32
#define OFF_BFC  512
#define OFF_SC   1024
#define OFF_SH   1536
#define OFF_SB   2048                               // B (8704)
#define OFF_TBUF (OFF_SB + 32 * SB_STR * 2)         // t (34816); phase-1 A overlays
#define OFF_SA   OFF_TBUF
#define SMEM_TOT (OFF_TBUF + 128 * TB_STR * 2)      // 45568 B

__global__ __launch_bounds__(256) void mma_layer_kernel(
    const __half* __restrict__ af,     // [3n][HD]
    const __half* __restrict__ wt,     // this layer: [4 slots][128][128]
    const float* __restrict__ bg,      // [3][HD]
    const float* __restrict__ bfc,
    const float* __restrict__ gamma, const float* __restrict__ beta,
    const float* __restrict__ mean,  const float* __restrict__ var,
    float* __restrict__ outf,          // fp32 output (layer 1) or null
    __half* __restrict__ outh,         // fp16 output (layer 0) or null
    int n)
{
    extern __shared__ char smem[];
    const uint32_t sb = smem_to_u32(smem);
    float* bgs  = (float*)(smem + OFF_BGS);
    float* bfcs = (float*)(smem + OFF_BFC);
    float* scs  = (float*)(smem + OFF_SC);
    float* shs  = (float*)(smem + OFF_SH);

    const int tid  = threadIdx.x;
    const int lane = tid & 31;
    const int wid  = tid >> 5;
    const int wm   = wid & 3;          // warp row  (m: 32 each)
    const int wn   = wid >> 2;         // warp col  (n: 64 each)
    const int bn0  = blockIdx.x * 128;

    if (tid < HD) {
        bgs[tid]  = __ldg(bg + tid) + __ldg(bg + HD + tid) + __ldg(bg + 2 * HD + tid);
        bfcs[tid] = __ldg(bfc + tid);
        float sc = __ldg(gamma + tid) * rsqrtf(__ldg(var + tid) + EPS);
        scs[tid] = sc;
        shs[tid] = __ldg(beta + tid) - __ldg(mean + tid) * sc;
    }

    const int lrow = lane & 15, lcol = lane >> 4;

    float acc[2][8][4];
    #pragma unroll
    for (int mi = 0; mi < 2; mi++)
        #pragma unroll
        for (int t = 0; t < 8; t++)
            #pragma unroll
            for (int q = 0; q < 4; q++) acc[mi][t][q] = 0.f;

    const int ar = tid >> 1, ahalf = tid & 1;        // A: 128 rows x 2 halves of 16
    const int br = tid >> 3, bc = tid & 7;           // B: 32 rows x 8 chunks of 16

    // ================= phase 1: 3 relations, K=128 each =======================
    for (int r = 0; r < 3; r++) {
        const __half* af_base = af + (size_t)r * n * HD;
        const __half* wp_base = wt + (size_t)r * 16384;
        for (int kc = 0; kc < 4; kc++) {
            __syncthreads();
            // stage A [128][32]
            {
                int gnode = bn0 + ar;
                uint4 v0 = {0,0,0,0}, v1 = {0,0,0,0};
                if (gnode < n) {
                    const uint4* ph = (const uint4*)(af_base + (size_t)gnode * HD + kc * 32 + ahalf * 16);
                    v0 = __ldg(ph); v1 = __ldg(ph + 1);
                }
                __half* dh = (__half*)(smem + OFF_SA) + ar * SA_STR + ahalf * 16;
                *(uint4*)dh = v0; *(uint4*)(dh + 8) = v1;
            }
            // stage B [32][128]
            {
                const uint4* ph = (const uint4*)(wp_base + (size_t)(kc * 32 + br) * HD + bc * 16);
                uint4 v0 = __ldg(ph), v1 = __ldg(ph + 1);
                __half* dh = (__half*)(smem + OFF_SB) + br * SB_STR + bc * 16;
                *(uint4*)dh = v0; *(uint4*)(dh + 8) = v1;
            }
            __syncthreads();

            #pragma unroll
            for (int kb = 0; kb < 32; kb += 16) {
                uint32_t ahf[2][4];
                #pragma unroll
                for (int mi = 0; mi < 2; mi++) {
                    uint32_t aoff = (uint32_t)((wm * 32 + mi * 16 + lrow) * SA_STR + kb + lcol * 8) * 2;
                    ldsm_x4(ahf[mi], sb + OFF_SA + aoff);
                }
                #pragma unroll
                for (int g = 0; g < 4; g++) {
                    uint32_t bh[4];
                    uint32_t boff = (uint32_t)((kb + lrow) * SB_STR + wn * 64 + g * 16 + lcol * 8) * 2;
                    ldsm_x4t(bh, sb + OFF_SB + boff);
                    #pragma unroll
                    for (int mi = 0; mi < 2; mi++) {
                        #pragma unroll
                        for (int nj = 0; nj < 2; nj++)
                            mma_f16(acc[mi][g * 2 + nj], ahf[mi], bh[nj * 2], bh[nj * 2 + 1]);
                    }
                }
            }
        }
    }

    // ================= transition: t = acc + bg -> tbuf (fp16) =================
    __syncthreads();
    {
        __half* th = (__half*)(smem + OFF_TBUF);
        #pragma unroll
        for (int mi = 0; mi < 2; mi++) {
            #pragma unroll
            for (int t = 0; t < 8; t++) {
                int g = t >> 1, nj = t & 1;
                int row0 = wm * 32 + mi * 16 + (lane >> 2);
                int col  = wn * 64 + g * 16 + nj * 8 + (lane & 3) * 2;
                float b0 = bgs[col], b1 = bgs[col + 1];
                #pragma unroll
                for (int half = 0; half < 2; half++) {
                    int row = row0 + half * 8;
                    __half2 hp = __floats2half2_rn(acc[mi][t][half * 2] + b0,
                                                   acc[mi][t][half * 2 + 1] + b1);
                    *(uint32_t*)(th + row * TB_STR + col) = *(uint32_t*)&hp;
                }
                #pragma unroll
                for (int q = 0; q < 4; q++) acc[mi][t][q] = 0.f;
            }
        }
    }

    // ================= phase 2: y = t @ Wfc =====================================
    {
        const __half* wp_base = wt + (size_t)3 * 16384;
        for (int kc = 0; kc < 4; kc++) {
            __syncthreads();
            {
                const uint4* ph = (const uint4*)(wp_base + (size_t)(kc * 32 + br) * HD + bc * 16);
                uint4 v0 = __ldg(ph), v1 = __ldg(ph + 1);
                __half* dh = (__half*)(smem + OFF_SB) + br * SB_STR + bc * 16;
                *(uint4*)dh = v0; *(uint4*)(dh + 8) = v1;
            }
            __syncthreads();

            #pragma unroll
            for (int kb2 = 0; kb2 < 32; kb2 += 16) {
                int kb = kc * 32 + kb2;
                uint32_t ahf[2][4];
                #pragma unroll
                for (int mi = 0; mi < 2; mi++) {
                    uint32_t aoff = (uint32_t)((wm * 32 + mi * 16 + lrow) * TB_STR + kb + lcol * 8) * 2;
                    ldsm_x4(ahf[mi], sb + OFF_TBUF + aoff);
                }
                #pragma unroll
                for (int g = 0; g < 4; g++) {
                    uint32_t bh[4];
                    uint32_t boff = (uint32_t)((kb2 + lrow) * SB_STR + wn * 64 + g * 16 + lcol * 8) * 2;
                    ldsm_x4t(bh, sb + OFF_SB + boff);
                    #pragma unroll
                    for (int mi = 0; mi < 2; mi++) {
                        #pragma unroll
                        for (int nj = 0; nj < 2; nj++)
                            mma_f16(acc[mi][g * 2 + nj], ahf[mi], bh[nj * 2], bh[nj * 2 + 1]);
                    }
                }
            }
        }
    }

    // ================= epilogue: ReLU + BN, store ==============================
    #pragma unroll
    for (int mi = 0; mi < 2; mi++) {
        #pragma unroll
        for (int t = 0; t < 8; t++) {
            int g = t >> 1, nj = t & 1;
            int row0 = wm * 32 + mi * 16 + (lane >> 2);
            int col  = wn * 64 + g * 16 + nj * 8 + (lane & 3) * 2;
            float bf0 = bfcs[col], bf1 = bfcs[col + 1];
            float sc0 = scs[col], sc1 = scs[col + 1];
            float sh0 = shs[col], sh1 = shs[col + 1];
            #pragma unroll
            for (int half = 0; half < 2; half++) {
                int node = bn0 + row0 + half * 8;
                if (node < n) {
                    float y0 = fmaxf(acc[mi][t][half * 2]     + bf0, 0.f);
                    float y1 = fmaxf(acc[mi][t][half * 2 + 1] + bf1, 0.f);
                    float v0 = y0 * sc0 + sh0;
                    float v1 = y1 * sc1 + sh1;
                    if (outh) {
                        __half2 hv = __floats2half2_rn(v0, v1);
                        *(uint32_t*)(outh + (size_t)node * HD + col) = *(uint32_t*)&hv;
                    } else {
                        *(float2*)(outf + (size_t)node * HD + col) = make_float2(v0, v1);
                    }
                }
            }
        }
    }
}

// ---------------- launch --------------------------------------------------------
extern "C" void kernel_launch(void* const* d_in, const int* in_sizes, int n_in,
                              void* d_out, int out_size)
{
    const float* x     = (const float*)d_in[0];
    const int* srcs[3] = {(const int*)d_in[1], (const int*)d_in[3], (const int*)d_in[5]};
    const int* dsts[3] = {(const int*)d_in[2], (const int*)d_in[4], (const int*)d_in[6]};
    const float* Wg0   = (const float*)d_in[7];
    const float* bg0   = (const float*)d_in[8];
    const float* Wg1   = (const float*)d_in[9];
    const float* bg1   = (const float*)d_in[10];
    const float* Wfc   = (const float*)d_in[11];
    const float* bfc   = (const float*)d_in[12];
    const float* gamma = (const float*)d_in[13];
    const float* beta  = (const float*)d_in[14];
    const float* mean  = (const float*)d_in[15];
    const float* var   = (const float*)d_in[16];

    int n = in_sizes[0] / HD;
    int es[3] = {in_sizes[1], in_sizes[3], in_sizes[5]};
    int emax = es[0] > es[1] ? es[0] : es[1];
    if (es[2] > emax) emax = es[2];

    int *p_deg, *p_off, *p_cur, *p_csum;
    int2* p_csr;
    __half *p_af, *p_wt, *p_xh, *p_h;
    cudaGetSymbolAddress((void**)&p_deg,  g_deg);
    cudaGetSymbolAddress((void**)&p_off,  g_off);
    cudaGetSymbolAddress((void**)&p_cur,  g_cur);
    cudaGetSymbolAddress((void**)&p_csum, g_csum);
    cudaGetSymbolAddress((void**)&p_csr,  g_csr);
    cudaGetSymbolAddress((void**)&p_af,   g_af);
    cudaGetSymbolAddress((void**)&p_wt,   g_wt);
    cudaGetSymbolAddress((void**)&p_xh,   g_xh);
    cudaGetSymbolAddress((void**)&p_h,    g_h);

    const int NT = 256;
    const int nchunks = (n + 255) / 256;

    cudaFuncSetAttribute(mma_layer_kernel, cudaFuncAttributeMaxDynamicSharedMemorySize, SMEM_TOT);

    // 0) fused util: zero deg, x->fp16, weight prep (1 launch)
    int c4 = n * HD / 4;
    int zb = (6 * n + 255) / 256;
    int xb = (c4 + 255) / 256;
    int ub = zb + xb + 512;
    prework_util_kernel<<<ub, 256>>>(p_deg, x, p_xh, Wg0, Wg1, Wfc, p_wt, n, c4, zb, xb);

    // 1) degrees (merged over relations); rsqrt folded into consumers
    {
        dim3 grid((emax + NT - 1) / NT, 3);
        count_pair3_kernel<<<grid, NT>>>(srcs[0], dsts[0], srcs[1], dsts[1], srcs[2], dsts[2],
                                         es[0], es[1], es[2], p_deg, n);
    }

    // 2) CSR by dst (parallel 3-kernel scan, per relation)
    for (int r = 0; r < 3; r++) {
        const int* deg_in  = p_deg + (size_t)(2 * r + 1) * n;
        const int* deg_out = p_deg + (size_t)2 * r * n;
        int* off  = p_off  + (size_t)r * (NMAX + 1);
        int* cur  = p_cur  + (size_t)r * NMAX;
        int* csum = p_csum + (size_t)r * 512;
        int2* csr = p_csr  + (size_t)r * EMAX;
        chunk_sum_kernel<<<nchunks, 256>>>(deg_in, csum, n);
        scan_chunks_kernel<<<1, 512>>>(csum, nchunks);
        write_offsets_kernel<<<nchunks, 256>>>(deg_in, csum, off, cur, n);
        csr_fill_kernel<<<(es[r] + NT - 1) / NT, NT>>>(
            srcs[r], dsts[r], deg_out, cur, csr, es[r]);
    }

    // 3) layers (per-relation gather launches — the proven form)
    int mblocks = (n + 127) / 128;
    for (int layer = 0; layer < 2; layer++) {
        const __half* hin = (layer == 0) ? p_xh : p_h;
        for (int r = 0; r < 3; r++) {
            long long thr = (long long)n * 32;
            int blocks = (int)((thr + NT - 1) / NT);
            gather_kernel<<<blocks, NT>>>(hin,
                                          p_csr + (size_t)r * EMAX,
                                          p_off + (size_t)r * (NMAX + 1),
                                          p_deg + (size_t)(2 * r + 1) * n,
                                          p_af + (size_t)r * n * HD, n);
        }
        mma_layer_kernel<<<mblocks, 256, SMEM_TOT>>>(
            p_af,
            p_wt + (size_t)layer * 4 * 16384,
            (layer == 0) ? bg0 : bg1,
            bfc + (size_t)layer * HD,
            gamma + (size_t)layer * HD, beta + (size_t)layer * HD,
            mean + (size_t)layer * HD, var + (size_t)layer * HD,
            (layer == 0) ? nullptr : (float*)d_out,
            (layer == 0) ? p_h : nullptr,
            n);
    }
}

// round 16
// speedup vs baseline: 1.0429x; 1.0111x over previous
#include <cuda_runtime.h>
#include <cuda_bf16.h>
#include <cuda_fp16.h>
#include <cstdint>

#define HD   128
#define NMAX 100000
#define EMAX 1700000
#define EPS  1e-5f

typedef unsigned long long ull;

// ---------------- scratch (__device__ globals; no runtime allocation) ----------
__device__ int    g_deg [6 * NMAX];                     // [out0,in0,out1,in1,out2,in2]
__device__ int    g_off [3 * (NMAX + 1)];
__device__ int    g_cur [3 * NMAX];
__device__ int    g_csum[3 * 512];
__device__ int2   g_csr [3 * (size_t)EMAX];             // (src, bits(rs_out[src]))
__device__ __half g_af  [(size_t)3 * NMAX * HD];        // agg (fp16)
__device__ __half g_wt  [2 * 4 * HD * HD];              // [layer][slot0..3][k][n] fp16
__device__ __half g_xh  [(size_t)NMAX * HD];            // fp16 copy of x
__device__ __half g_h   [(size_t)NMAX * HD];            // layer-0 output (fp16)

// ---------------- mma.sync / ldmatrix helpers (portable sm_80+ PTX) -------------
__device__ __forceinline__ uint32_t smem_to_u32(const void* p) {
    uint32_t a;
    asm("{ .reg .u64 t; cvta.to.shared.u64 t, %1; cvt.u32.u64 %0, t; }" : "=r"(a) : "l"(p));
    return a;
}
__device__ __forceinline__ void ldsm_x4(uint32_t r[4], uint32_t addr) {
    asm volatile("ldmatrix.sync.aligned.m8n8.x4.shared.b16 {%0,%1,%2,%3}, [%4];"
                 : "=r"(r[0]), "=r"(r[1]), "=r"(r[2]), "=r"(r[3]) : "r"(addr));
}
__device__ __forceinline__ void ldsm_x4t(uint32_t r[4], uint32_t addr) {
    asm volatile("ldmatrix.sync.aligned.m8n8.x4.trans.shared.b16 {%0,%1,%2,%3}, [%4];"
                 : "=r"(r[0]), "=r"(r[1]), "=r"(r[2]), "=r"(r[3]) : "r"(addr));
}
__device__ __forceinline__ void mma_f16(float c[4], const uint32_t a[4], uint32_t b0, uint32_t b1) {
    asm volatile("mma.sync.aligned.m16n8k16.row.col.f32.f16.f16.f32 "
                 "{%0,%1,%2,%3}, {%4,%5,%6,%7}, {%8,%9}, {%0,%1,%2,%3};"
                 : "+f"(c[0]), "+f"(c[1]), "+f"(c[2]), "+f"(c[3])
                 : "r"(a[0]), "r"(a[1]), "r"(a[2]), "r"(a[3]), "r"(b0), "r"(b1));
}

// ---------------- fused util: zero deg, x -> fp16, weight prep ------------------
__global__ void prework_util_kernel(int* __restrict__ deg,
                                    const float* __restrict__ x, __half* __restrict__ xh,
                                    const float* __restrict__ Wg0, const float* __restrict__ Wg1,
                                    const float* __restrict__ Wfc, __half* __restrict__ wt,
                                    int n, int c4, int zb, int xb) {
    int b = blockIdx.x;
    if (b < zb) {
        int i = b * 256 + threadIdx.x;
        if (i < 6 * n) deg[i] = 0;
    } else if (b < zb + xb) {
        int i = (b - zb) * 256 + threadIdx.x;
        if (i < c4) {
            float4 v = __ldg((const float4*)x + i);
            __half2 p0 = __floats2half2_rn(v.x, v.y);
            __half2 p1 = __floats2half2_rn(v.z, v.w);
            uint2 o = make_uint2(*(uint32_t*)&p0, *(uint32_t*)&p1);
            ((uint2*)xh)[i] = o;
        }
    } else {
        int idx = (b - zb - xb) * 256 + threadIdx.x;
        if (idx < 2 * 4 * 16384) {
            int kn = idx & 16383;
            int slot = (idx >> 14) & 3;
            int layer = idx >> 16;
            float v;
            if (slot < 3) v = (layer ? Wg1 : Wg0)[(size_t)slot * 16384 + kn];
            else          v = Wfc[(size_t)layer * 16384 + kn];
            wt[(size_t)(layer * 4 + slot) * 16384 + kn] = __float2half_rn(v);
        }
    }
}

// merged over 3 relations via blockIdx.y (measured win: 51us vs 3x21us)
__global__ void count_pair3_kernel(const int* __restrict__ s0, const int* __restrict__ d0,
                                   const int* __restrict__ s1, const int* __restrict__ d1,
                                   const int* __restrict__ s2, const int* __restrict__ d2,
                                   int e0, int e1, int e2,
                                   int* __restrict__ deg, int n) {
    int r = blockIdx.y;
    const int* src = (r == 0) ? s0 : (r == 1) ? s1 : s2;
    const int* dst = (r == 0) ? d0 : (r == 1) ? d1 : d2;
    int e = (r == 0) ? e0 : (r == 1) ? e1 : e2;
    int i = blockIdx.x * blockDim.x + threadIdx.x;
    if (i >= e) return;
    atomicAdd(deg + (size_t)2 * r * n + src[i], 1);
    atomicAdd(deg + (size_t)(2 * r + 1) * n + dst[i], 1);
}

// ---------------- CSR build (per relation; scans merged into one 3-block launch) -
__global__ void chunk_sum_kernel(const int* __restrict__ deg, int* __restrict__ csum, int n) {
    __shared__ int s[256];
    int i = blockIdx.x * 256 + threadIdx.x;
    s[threadIdx.x] = (i < n) ? deg[i] : 0;
    __syncthreads();
    #pragma unroll
    for (int st = 128; st > 0; st >>= 1) {
        if (threadIdx.x < st) s[threadIdx.x] += s[threadIdx.x + st];
        __syncthreads();
    }
    if (threadIdx.x == 0) csum[blockIdx.x] = s[0];
}

// one block per relation: block b scans csum[b*512 .. b*512+nc)
__global__ void scan3_kernel(int* __restrict__ csum, int nc) {
    __shared__ int s[512];
    int* cs = csum + (size_t)blockIdx.x * 512;
    int t = threadIdx.x;
    int v0 = (t < nc) ? cs[t] : 0;
    s[t] = v0;
    __syncthreads();
    #pragma unroll
    for (int off = 1; off < 512; off <<= 1) {
        int v = (t >= off) ? s[t - off] : 0;
        __syncthreads();
        s[t] += v;
        __syncthreads();
    }
    if (t < nc) cs[t] = s[t] - v0;
}

__global__ void write_offsets_kernel(const int* __restrict__ deg, const int* __restrict__ csum,
                                     int* __restrict__ off, int* __restrict__ cur, int n) {
    __shared__ int s[256];
    int t = threadIdx.x;
    int i = blockIdx.x * 256 + t;
    int d = (i < n) ? deg[i] : 0;
    s[t] = d;
    __syncthreads();
    #pragma unroll
    for (int o = 1; o < 256; o <<= 1) {
        int v = (t >= o) ? s[t - o] : 0;
        __syncthreads();
        s[t] += v;
        __syncthreads();
    }
    int excl = s[t] - d + csum[blockIdx.x];
    if (i < n) {
        off[i] = excl;
        cur[i] = excl;
        if (i == n - 1) off[n] = excl + d;
    }
}

// rs_out folded: compute rsqrt from deg_out directly
__global__ void csr_fill_kernel(const int* __restrict__ src, const int* __restrict__ dst,
                                const int* __restrict__ deg_out,
                                int* __restrict__ cur, int2* __restrict__ csr, int e) {
    int i = blockIdx.x * blockDim.x + threadIdx.x;
    if (i >= e) return;
    int s = src[i];
    int d = __ldg(deg_out + s);
    float c = rsqrtf((float)(d < 1 ? 1 : d));
    int slot = atomicAdd(cur + dst[i], 1);
    csr[slot] = make_int2(s, __float_as_int(c));
}

// ---------------- gather (per relation): agg[d] = rs_in[d] * sum rs_out[s] h[s] -
__global__ void gather_kernel(const __half* __restrict__ h,
                              const int2* __restrict__ csr, const int* __restrict__ off,
                              const int* __restrict__ deg_in,
                              __half* __restrict__ af, int n) {
    int w    = (blockIdx.x * blockDim.x + threadIdx.x) >> 5;
    int lane = threadIdx.x & 31;
    if (w >= n) return;
    int e0 = __ldg(off + w), e1 = __ldg(off + w + 1);
    float4 acc = make_float4(0.f, 0.f, 0.f, 0.f);
    int e = e0;
    for (; e + 1 < e1; e += 2) {
        int2 ea = __ldg(csr + e), eb = __ldg(csr + e + 1);
        float ca = __int_as_float(ea.y), cb = __int_as_float(eb.y);
        uint2 ra = __ldg((const uint2*)(h + (size_t)ea.x * HD) + lane);
        uint2 rb = __ldg((const uint2*)(h + (size_t)eb.x * HD) + lane);
        float2 a0 = __half22float2(*(__half2*)&ra.x), a1 = __half22float2(*(__half2*)&ra.y);
        float2 b0 = __half22float2(*(__half2*)&rb.x), b1 = __half22float2(*(__half2*)&rb.y);
        acc.x = fmaf(a0.x, ca, acc.x); acc.y = fmaf(a0.y, ca, acc.y);
        acc.z = fmaf(a1.x, ca, acc.z); acc.w = fmaf(a1.y, ca, acc.w);
        acc.x = fmaf(b0.x, cb, acc.x); acc.y = fmaf(b0.y, cb, acc.y);
        acc.z = fmaf(b1.x, cb, acc.z); acc.w = fmaf(b1.y, cb, acc.w);
    }
    if (e < e1) {
        int2 ea = __ldg(csr + e);
        float ca = __int_as_float(ea.y);
        uint2 ra = __ldg((const uint2*)(h + (size_t)ea.x * HD) + lane);
        float2 a0 = __half22float2(*(__half2*)&ra.x), a1 = __half22float2(*(__half2*)&ra.y);
        acc.x = fmaf(a0.x, ca, acc.x); acc.y = fmaf(a0.y, ca, acc.y);
        acc.z = fmaf(a1.x, ca, acc.z); acc.w = fmaf(a1.y, ca, acc.w);
    }
    int din = __ldg(deg_in + w);
    float ri = rsqrtf((float)(din < 1 ? 1 : din));
    __half2 p0 = __floats2half2_rn(acc.x * ri, acc.y * ri);
    __half2 p1 = __floats2half2_rn(acc.z * ri, acc.w * ri);
    uint2 hv = make_uint2(*(uint32_t*)&p0, *(uint32_t*)&p1);
    ((uint2*)(af + (size_t)w * HD))[lane] = hv;
}

// ---------------- fused mma.sync layer kernel (single-pass fp16) ----------------
// Block = 128 nodes x 128 outputs, 256 threads (8 warps, 4m x 2n, warp tile 32x64).

#define SA_STR 40      // phase-1 A row stride (fp16): 128x40
#define SB_STR 136     // B row stride (fp16): 32x136
#define TB_STR 136     // tbuf row stride (fp16): 128x136

#define OFF_BGS  0                                  // 128 f32
#define OFF_BFC  512
#define OFF_SC   1024
#define OFF_SH   1536
#define OFF_SB   2048                               // B (8704)
#define OFF_TBUF (OFF_SB + 32 * SB_STR * 2)         // t (34816); phase-1 A overlays
#define OFF_SA   OFF_TBUF
#define SMEM_TOT (OFF_TBUF + 128 * TB_STR * 2)      // 45568 B

__global__ __launch_bounds__(256) void mma_layer_kernel(
    const __half* __restrict__ af,     // [3n][HD]
    const __half* __restrict__ wt,     // this layer: [4 slots][128][128]
    const float* __restrict__ bg,      // [3][HD]
    const float* __restrict__ bfc,
    const float* __restrict__ gamma, const float* __restrict__ beta,
    const float* __restrict__ mean,  const float* __restrict__ var,
    float* __restrict__ outf,          // fp32 output (layer 1) or null
    __half* __restrict__ outh,         // fp16 output (layer 0) or null
    int n)
{
    extern __shared__ char smem[];
    const uint32_t sb = smem_to_u32(smem);
    float* bgs  = (float*)(smem + OFF_BGS);
    float* bfcs = (float*)(smem + OFF_BFC);
    float* scs  = (float*)(smem + OFF_SC);
    float* shs  = (float*)(smem + OFF_SH);

    const int tid  = threadIdx.x;
    const int lane = tid & 31;
    const int wid  = tid >> 5;
    const int wm   = wid & 3;          // warp row  (m: 32 each)
    const int wn   = wid >> 2;         // warp col  (n: 64 each)
    const int bn0  = blockIdx.x * 128;

    if (tid < HD) {
        bgs[tid]  = __ldg(bg + tid) + __ldg(bg + HD + tid) + __ldg(bg + 2 * HD + tid);
        bfcs[tid] = __ldg(bfc + tid);
        float sc = __ldg(gamma + tid) * rsqrtf(__ldg(var + tid) + EPS);
        scs[tid] = sc;
        shs[tid] = __ldg(beta + tid) - __ldg(mean + tid) * sc;
    }

    const int lrow = lane & 15, lcol = lane >> 4;

    float acc[2][8][4];
    #pragma unroll
    for (int mi = 0; mi < 2; mi++)
        #pragma unroll
        for (int t = 0; t < 8; t++)
            #pragma unroll
            for (int q = 0; q < 4; q++) acc[mi][t][q] = 0.f;

    const int ar = tid >> 1, ahalf = tid & 1;        // A: 128 rows x 2 halves of 16
    const int br = tid >> 3, bc = tid & 7;           // B: 32 rows x 8 chunks of 16

    // ================= phase 1: 3 relations, K=128 each =======================
    for (int r = 0; r < 3; r++) {
        const __half* af_base = af + (size_t)r * n * HD;
        const __half* wp_base = wt + (size_t)r * 16384;
        for (int kc = 0; kc < 4; kc++) {
            __syncthreads();
            // stage A [128][32]
            {
                int gnode = bn0 + ar;
                uint4 v0 = {0,0,0,0}, v1 = {0,0,0,0};
                if (gnode < n) {
                    const uint4* ph = (const uint4*)(af_base + (size_t)gnode * HD + kc * 32 + ahalf * 16);
                    v0 = __ldg(ph); v1 = __ldg(ph + 1);
                }
                __half* dh = (__half*)(smem + OFF_SA) + ar * SA_STR + ahalf * 16;
                *(uint4*)dh = v0; *(uint4*)(dh + 8) = v1;
            }
            // stage B [32][128]
            {
                const uint4* ph = (const uint4*)(wp_base + (size_t)(kc * 32 + br) * HD + bc * 16);
                uint4 v0 = __ldg(ph), v1 = __ldg(ph + 1);
                __half* dh = (__half*)(smem + OFF_SB) + br * SB_STR + bc * 16;
                *(uint4*)dh = v0; *(uint4*)(dh + 8) = v1;
            }
            __syncthreads();

            #pragma unroll
            for (int kb = 0; kb < 32; kb += 16) {
                uint32_t ahf[2][4];
                #pragma unroll
                for (int mi = 0; mi < 2; mi++) {
                    uint32_t aoff = (uint32_t)((wm * 32 + mi * 16 + lrow) * SA_STR + kb + lcol * 8) * 2;
                    ldsm_x4(ahf[mi], sb + OFF_SA + aoff);
                }
                #pragma unroll
                for (int g = 0; g < 4; g++) {
                    uint32_t bh[4];
                    uint32_t boff = (uint32_t)((kb + lrow) * SB_STR + wn * 64 + g * 16 + lcol * 8) * 2;
                    ldsm_x4t(bh, sb + OFF_SB + boff);
                    #pragma unroll
                    for (int mi = 0; mi < 2; mi++) {
                        #pragma unroll
                        for (int nj = 0; nj < 2; nj++)
                            mma_f16(acc[mi][g * 2 + nj], ahf[mi], bh[nj * 2], bh[nj * 2 + 1]);
                    }
                }
            }
        }
    }

    // ================= transition: t = acc + bg -> tbuf (fp16) =================
    __syncthreads();
    {
        __half* th = (__half*)(smem + OFF_TBUF);
        #pragma unroll
        for (int mi = 0; mi < 2; mi++) {
            #pragma unroll
            for (int t = 0; t < 8; t++) {
                int g = t >> 1, nj = t & 1;
                int row0 = wm * 32 + mi * 16 + (lane >> 2);
                int col  = wn * 64 + g * 16 + nj * 8 + (lane & 3) * 2;
                float b0 = bgs[col], b1 = bgs[col + 1];
                #pragma unroll
                for (int half = 0; half < 2; half++) {
                    int row = row0 + half * 8;
                    __half2 hp = __floats2half2_rn(acc[mi][t][half * 2] + b0,
                                                   acc[mi][t][half * 2 + 1] + b1);
                    *(uint32_t*)(th + row * TB_STR + col) = *(uint32_t*)&hp;
                }
                #pragma unroll
                for (int q = 0; q < 4; q++) acc[mi][t][q] = 0.f;
            }
        }
    }

    // ================= phase 2: y = t @ Wfc =====================================
    {
        const __half* wp_base = wt + (size_t)3 * 16384;
        for (int kc = 0; kc < 4; kc++) {
            __syncthreads();
            {
                const uint4* ph = (const uint4*)(wp_base + (size_t)(kc * 32 + br) * HD + bc * 16);
                uint4 v0 = __ldg(ph), v1 = __ldg(ph + 1);
                __half* dh = (__half*)(smem + OFF_SB) + br * SB_STR + bc * 16;
                *(uint4*)dh = v0; *(uint4*)(dh + 8) = v1;
            }
            __syncthreads();

            #pragma unroll
            for (int kb2 = 0; kb2 < 32; kb2 += 16) {
                int kb = kc * 32 + kb2;
                uint32_t ahf[2][4];
                #pragma unroll
                for (int mi = 0; mi < 2; mi++) {
                    uint32_t aoff = (uint32_t)((wm * 32 + mi * 16 + lrow) * TB_STR + kb + lcol * 8) * 2;
                    ldsm_x4(ahf[mi], sb + OFF_TBUF + aoff);
                }
                #pragma unroll
                for (int g = 0; g < 4; g++) {
                    uint32_t bh[4];
                    uint32_t boff = (uint32_t)((kb2 + lrow) * SB_STR + wn * 64 + g * 16 + lcol * 8) * 2;
                    ldsm_x4t(bh, sb + OFF_SB + boff);
                    #pragma unroll
                    for (int mi = 0; mi < 2; mi++) {
                        #pragma unroll
                        for (int nj = 0; nj < 2; nj++)
                            mma_f16(acc[mi][g * 2 + nj], ahf[mi], bh[nj * 2], bh[nj * 2 + 1]);
                    }
                }
            }
        }
    }

    // ================= epilogue: ReLU + BN, store ==============================
    #pragma unroll
    for (int mi = 0; mi < 2; mi++) {
        #pragma unroll
        for (int t = 0; t < 8; t++) {
            int g = t >> 1, nj = t & 1;
            int row0 = wm * 32 + mi * 16 + (lane >> 2);
            int col  = wn * 64 + g * 16 + nj * 8 + (lane & 3) * 2;
            float bf0 = bfcs[col], bf1 = bfcs[col + 1];
            float sc0 = scs[col], sc1 = scs[col + 1];
            float sh0 = shs[col], sh1 = shs[col + 1];
            #pragma unroll
            for (int half = 0; half < 2; half++) {
                int node = bn0 + row0 + half * 8;
                if (node < n) {
                    float y0 = fmaxf(acc[mi][t][half * 2]     + bf0, 0.f);
                    float y1 = fmaxf(acc[mi][t][half * 2 + 1] + bf1, 0.f);
                    float v0 = y0 * sc0 + sh0;
                    float v1 = y1 * sc1 + sh1;
                    if (outh) {
                        __half2 hv = __floats2half2_rn(v0, v1);
                        *(uint32_t*)(outh + (size_t)node * HD + col) = *(uint32_t*)&hv;
                    } else {
                        *(float2*)(outf + (size_t)node * HD + col) = make_float2(v0, v1);
                    }
                }
            }
        }
    }
}

// ---------------- launch --------------------------------------------------------
extern "C" void kernel_launch(void* const* d_in, const int* in_sizes, int n_in,
                              void* d_out, int out_size)
{
    const float* x     = (const float*)d_in[0];
    const int* srcs[3] = {(const int*)d_in[1], (const int*)d_in[3], (const int*)d_in[5]};
    const int* dsts[3] = {(const int*)d_in[2], (const int*)d_in[4], (const int*)d_in[6]};
    const float* Wg0   = (const float*)d_in[7];
    const float* bg0   = (const float*)d_in[8];
    const float* Wg1   = (const float*)d_in[9];
    const float* bg1   = (const float*)d_in[10];
    const float* Wfc   = (const float*)d_in[11];
    const float* bfc   = (const float*)d_in[12];
    const float* gamma = (const float*)d_in[13];
    const float* beta  = (const float*)d_in[14];
    const float* mean  = (const float*)d_in[15];
    const float* var   = (const float*)d_in[16];

    int n = in_sizes[0] / HD;
    int es[3] = {in_sizes[1], in_sizes[3], in_sizes[5]};
    int emax = es[0] > es[1] ? es[0] : es[1];
    if (es[2] > emax) emax = es[2];

    int *p_deg, *p_off, *p_cur, *p_csum;
    int2* p_csr;
    __half *p_af, *p_wt, *p_xh, *p_h;
    cudaGetSymbolAddress((void**)&p_deg,  g_deg);
    cudaGetSymbolAddress((void**)&p_off,  g_off);
    cudaGetSymbolAddress((void**)&p_cur,  g_cur);
    cudaGetSymbolAddress((void**)&p_csum, g_csum);
    cudaGetSymbolAddress((void**)&p_csr,  g_csr);
    cudaGetSymbolAddress((void**)&p_af,   g_af);
    cudaGetSymbolAddress((void**)&p_wt,   g_wt);
    cudaGetSymbolAddress((void**)&p_xh,   g_xh);
    cudaGetSymbolAddress((void**)&p_h,    g_h);

    const int NT = 256;
    const int nchunks = (n + 255) / 256;

    cudaFuncSetAttribute(mma_layer_kernel, cudaFuncAttributeMaxDynamicSharedMemorySize, SMEM_TOT);

    // 0) fused util: zero deg, x->fp16, weight prep (1 launch)
    int c4 = n * HD / 4;
    int zb = (6 * n + 255) / 256;
    int xb = (c4 + 255) / 256;
    int ub = zb + xb + 512;
    prework_util_kernel<<<ub, 256>>>(p_deg, x, p_xh, Wg0, Wg1, Wfc, p_wt, n, c4, zb, xb);

    // 1) degrees (merged over relations); rsqrt folded into consumers
    {
        dim3 grid((emax + NT - 1) / NT, 3);
        count_pair3_kernel<<<grid, NT>>>(srcs[0], dsts[0], srcs[1], dsts[1], srcs[2], dsts[2],
                                         es[0], es[1], es[2], p_deg, n);
    }

    // 2) CSR by dst: per-relation chunk sums, ONE merged 3-block scan, then
    //    per-relation offsets + fill
    for (int r = 0; r < 3; r++)
        chunk_sum_kernel<<<nchunks, 256>>>(p_deg + (size_t)(2 * r + 1) * n,
                                           p_csum + (size_t)r * 512, n);
    scan3_kernel<<<3, 512>>>(p_csum, nchunks);
    for (int r = 0; r < 3; r++) {
        const int* deg_in  = p_deg + (size_t)(2 * r + 1) * n;
        const int* deg_out = p_deg + (size_t)2 * r * n;
        int* off  = p_off  + (size_t)r * (NMAX + 1);
        int* cur  = p_cur  + (size_t)r * NMAX;
        int* csum = p_csum + (size_t)r * 512;
        int2* csr = p_csr  + (size_t)r * EMAX;
        write_offsets_kernel<<<nchunks, 256>>>(deg_in, csum, off, cur, n);
        csr_fill_kernel<<<(es[r] + NT - 1) / NT, NT>>>(
            srcs[r], dsts[r], deg_out, cur, csr, es[r]);
    }

    // 3) layers (per-relation gather launches — the proven form)
    int mblocks = (n + 127) / 128;
    for (int layer = 0; layer < 2; layer++) {
        const __half* hin = (layer == 0) ? p_xh : p_h;
        for (int r = 0; r < 3; r++) {
            long long thr = (long long)n * 32;
            int blocks = (int)((thr + NT - 1) / NT);
            gather_kernel<<<blocks, NT>>>(hin,
                                          p_csr + (size_t)r * EMAX,
                                          p_off + (size_t)r * (NMAX + 1),
                                          p_deg + (size_t)(2 * r + 1) * n,
                                          p_af + (size_t)r * n * HD, n);
        }
        mma_layer_kernel<<<mblocks, 256, SMEM_TOT>>>(
            p_af,
            p_wt + (size_t)layer * 4 * 16384,
            (layer == 0) ? bg0 : bg1,
            bfc + (size_t)layer * HD,
            gamma + (size_t)layer * HD, beta + (size_t)layer * HD,
            mean + (size_t)layer * HD, var + (size_t)layer * HD,
            (layer == 0) ? nullptr : (float*)d_out,
            (layer == 0) ? p_h : nullptr,
            n);
    }
}

// round 17
// speedup vs baseline: 1.0566x; 1.0131x over previous
#include <cuda_runtime.h>
#include <cuda_bf16.h>
#include <cuda_fp16.h>
#include <cstdint>

#define HD   128
#define NMAX 100000
#define EMAX 1700000
#define EPS  1e-5f

typedef unsigned long long ull;

// ---------------- scratch (__device__ globals; no runtime allocation) ----------
__device__ int    g_deg [6 * NMAX];                     // [out0,in0,out1,in1,out2,in2]
__device__ int    g_off [3 * (NMAX + 1)];
__device__ int    g_cur [3 * NMAX];
__device__ int    g_csum[3 * 512];
__device__ int2   g_csr [3 * (size_t)EMAX];             // (src, bits(rs_out[src]))
__device__ __half g_af  [(size_t)3 * NMAX * HD];        // agg (fp16)
__device__ __half g_wt  [2 * 4 * HD * HD];              // [layer][slot0..3][k][n] fp16
__device__ __half g_xh  [(size_t)NMAX * HD];            // fp16 copy of x
__device__ __half g_h   [(size_t)NMAX * HD];            // layer-0 output (fp16)

// ---------------- mma.sync / ldmatrix helpers (portable sm_80+ PTX) -------------
__device__ __forceinline__ uint32_t smem_to_u32(const void* p) {
    uint32_t a;
    asm("{ .reg .u64 t; cvta.to.shared.u64 t, %1; cvt.u32.u64 %0, t; }" : "=r"(a) : "l"(p));
    return a;
}
__device__ __forceinline__ void ldsm_x4(uint32_t r[4], uint32_t addr) {
    asm volatile("ldmatrix.sync.aligned.m8n8.x4.shared.b16 {%0,%1,%2,%3}, [%4];"
                 : "=r"(r[0]), "=r"(r[1]), "=r"(r[2]), "=r"(r[3]) : "r"(addr));
}
__device__ __forceinline__ void ldsm_x4t(uint32_t r[4], uint32_t addr) {
    asm volatile("ldmatrix.sync.aligned.m8n8.x4.trans.shared.b16 {%0,%1,%2,%3}, [%4];"
                 : "=r"(r[0]), "=r"(r[1]), "=r"(r[2]), "=r"(r[3]) : "r"(addr));
}
__device__ __forceinline__ void mma_f16(float c[4], const uint32_t a[4], uint32_t b0, uint32_t b1) {
    asm volatile("mma.sync.aligned.m16n8k16.row.col.f32.f16.f16.f32 "
                 "{%0,%1,%2,%3}, {%4,%5,%6,%7}, {%8,%9}, {%0,%1,%2,%3};"
                 : "+f"(c[0]), "+f"(c[1]), "+f"(c[2]), "+f"(c[3])
                 : "r"(a[0]), "r"(a[1]), "r"(a[2]), "r"(a[3]), "r"(b0), "r"(b1));
}

// ---------------- fused util: zero deg, x -> fp16, weight prep ------------------
__global__ void prework_util_kernel(int* __restrict__ deg,
                                    const float* __restrict__ x, __half* __restrict__ xh,
                                    const float* __restrict__ Wg0, const float* __restrict__ Wg1,
                                    const float* __restrict__ Wfc, __half* __restrict__ wt,
                                    int n, int c4, int zb, int xb) {
    int b = blockIdx.x;
    if (b < zb) {
        int i = b * 256 + threadIdx.x;
        if (i < 6 * n) deg[i] = 0;
    } else if (b < zb + xb) {
        int i = (b - zb) * 256 + threadIdx.x;
        if (i < c4) {
            float4 v = __ldg((const float4*)x + i);
            __half2 p0 = __floats2half2_rn(v.x, v.y);
            __half2 p1 = __floats2half2_rn(v.z, v.w);
            uint2 o = make_uint2(*(uint32_t*)&p0, *(uint32_t*)&p1);
            ((uint2*)xh)[i] = o;
        }
    } else {
        int idx = (b - zb - xb) * 256 + threadIdx.x;
        if (idx < 2 * 4 * 16384) {
            int kn = idx & 16383;
            int slot = (idx >> 14) & 3;
            int layer = idx >> 16;
            float v;
            if (slot < 3) v = (layer ? Wg1 : Wg0)[(size_t)slot * 16384 + kn];
            else          v = Wfc[(size_t)layer * 16384 + kn];
            wt[(size_t)(layer * 4 + slot) * 16384 + kn] = __float2half_rn(v);
        }
    }
}

// merged over 3 relations via blockIdx.y (measured win: 51us vs 3x21us)
__global__ void count_pair3_kernel(const int* __restrict__ s0, const int* __restrict__ d0,
                                   const int* __restrict__ s1, const int* __restrict__ d1,
                                   const int* __restrict__ s2, const int* __restrict__ d2,
                                   int e0, int e1, int e2,
                                   int* __restrict__ deg, int n) {
    int r = blockIdx.y;
    const int* src = (r == 0) ? s0 : (r == 1) ? s1 : s2;
    const int* dst = (r == 0) ? d0 : (r == 1) ? d1 : d2;
    int e = (r == 0) ? e0 : (r == 1) ? e1 : e2;
    int i = blockIdx.x * blockDim.x + threadIdx.x;
    if (i >= e) return;
    atomicAdd(deg + (size_t)2 * r * n + src[i], 1);
    atomicAdd(deg + (size_t)(2 * r + 1) * n + dst[i], 1);
}

// ---------------- CSR build: node-scale stages merged via blockIdx.y ------------
__global__ void chunk_sum3_kernel(const int* __restrict__ deg, int* __restrict__ csum, int n) {
    __shared__ int s[256];
    int r = blockIdx.y;
    const int* dg = deg + (size_t)(2 * r + 1) * n;
    int* cs = csum + (size_t)r * 512;
    int i = blockIdx.x * 256 + threadIdx.x;
    s[threadIdx.x] = (i < n) ? dg[i] : 0;
    __syncthreads();
    #pragma unroll
    for (int st = 128; st > 0; st >>= 1) {
        if (threadIdx.x < st) s[threadIdx.x] += s[threadIdx.x + st];
        __syncthreads();
    }
    if (threadIdx.x == 0) cs[blockIdx.x] = s[0];
}

// one block per relation
__global__ void scan3_kernel(int* __restrict__ csum, int nc) {
    __shared__ int s[512];
    int* cs = csum + (size_t)blockIdx.x * 512;
    int t = threadIdx.x;
    int v0 = (t < nc) ? cs[t] : 0;
    s[t] = v0;
    __syncthreads();
    #pragma unroll
    for (int off = 1; off < 512; off <<= 1) {
        int v = (t >= off) ? s[t - off] : 0;
        __syncthreads();
        s[t] += v;
        __syncthreads();
    }
    if (t < nc) cs[t] = s[t] - v0;
}

__global__ void write_offsets3_kernel(const int* __restrict__ deg, const int* __restrict__ csum,
                                      int* __restrict__ offb, int* __restrict__ curb, int n) {
    __shared__ int s[256];
    int r = blockIdx.y;
    const int* dg = deg + (size_t)(2 * r + 1) * n;
    const int* cs = csum + (size_t)r * 512;
    int* off = offb + (size_t)r * (NMAX + 1);
    int* cur = curb + (size_t)r * NMAX;
    int t = threadIdx.x;
    int i = blockIdx.x * 256 + t;
    int d = (i < n) ? dg[i] : 0;
    s[t] = d;
    __syncthreads();
    #pragma unroll
    for (int o = 1; o < 256; o <<= 1) {
        int v = (t >= o) ? s[t - o] : 0;
        __syncthreads();
        s[t] += v;
        __syncthreads();
    }
    int excl = s[t] - d + cs[blockIdx.x];
    if (i < n) {
        off[i] = excl;
        cur[i] = excl;
        if (i == n - 1) off[n] = excl + d;
    }
}

// rs_out folded: compute rsqrt from deg_out directly (edge-scale: per relation)
__global__ void csr_fill_kernel(const int* __restrict__ src, const int* __restrict__ dst,
                                const int* __restrict__ deg_out,
                                int* __restrict__ cur, int2* __restrict__ csr, int e) {
    int i = blockIdx.x * blockDim.x + threadIdx.x;
    if (i >= e) return;
    int s = src[i];
    int d = __ldg(deg_out + s);
    float c = rsqrtf((float)(d < 1 ? 1 : d));
    int slot = atomicAdd(cur + dst[i], 1);
    csr[slot] = make_int2(s, __float_as_int(c));
}

// ---------------- gather (per relation): agg[d] = rs_in[d] * sum rs_out[s] h[s] -
__global__ void gather_kernel(const __half* __restrict__ h,
                              const int2* __restrict__ csr, const int* __restrict__ off,
                              const int* __restrict__ deg_in,
                              __half* __restrict__ af, int n) {
    int w    = (blockIdx.x * blockDim.x + threadIdx.x) >> 5;
    int lane = threadIdx.x & 31;
    if (w >= n) return;
    int e0 = __ldg(off + w), e1 = __ldg(off + w + 1);
    float4 acc = make_float4(0.f, 0.f, 0.f, 0.f);
    int e = e0;
    for (; e + 1 < e1; e += 2) {
        int2 ea = __ldg(csr + e), eb = __ldg(csr + e + 1);
        float ca = __int_as_float(ea.y), cb = __int_as_float(eb.y);
        uint2 ra = __ldg((const uint2*)(h + (size_t)ea.x * HD) + lane);
        uint2 rb = __ldg((const uint2*)(h + (size_t)eb.x * HD) + lane);
        float2 a0 = __half22float2(*(__half2*)&ra.x), a1 = __half22float2(*(__half2*)&ra.y);
        float2 b0 = __half22float2(*(__half2*)&rb.x), b1 = __half22float2(*(__half2*)&rb.y);
        acc.x = fmaf(a0.x, ca, acc.x); acc.y = fmaf(a0.y, ca, acc.y);
        acc.z = fmaf(a1.x, ca, acc.z); acc.w = fmaf(a1.y, ca, acc.w);
        acc.x = fmaf(b0.x, cb, acc.x); acc.y = fmaf(b0.y, cb, acc.y);
        acc.z = fmaf(b1.x, cb, acc.z); acc.w = fmaf(b1.y, cb, acc.w);
    }
    if (e < e1) {
        int2 ea = __ldg(csr + e);
        float ca = __int_as_float(ea.y);
        uint2 ra = __ldg((const uint2*)(h + (size_t)ea.x * HD) + lane);
        float2 a0 = __half22float2(*(__half2*)&ra.x), a1 = __half22float2(*(__half2*)&ra.y);
        acc.x = fmaf(a0.x, ca, acc.x); acc.y = fmaf(a0.y, ca, acc.y);
        acc.z = fmaf(a1.x, ca, acc.z); acc.w = fmaf(a1.y, ca, acc.w);
    }
    int din = __ldg(deg_in + w);
    float ri = rsqrtf((float)(din < 1 ? 1 : din));
    __half2 p0 = __floats2half2_rn(acc.x * ri, acc.y * ri);
    __half2 p1 = __floats2half2_rn(acc.z * ri, acc.w * ri);
    uint2 hv = make_uint2(*(uint32_t*)&p0, *(uint32_t*)&p1);
    ((uint2*)(af + (size_t)w * HD))[lane] = hv;
}

// ---------------- fused mma.sync layer kernel (single-pass fp16) ----------------
// Block = 128 nodes x 128 outputs, 256 threads (8 warps, 4m x 2n, warp tile 32x64).

#define SA_STR 40      // phase-1 A row stride (fp16): 128x40
#define SB_STR 136     // B row stride (fp16): 32x136
#define TB_STR 136     // tbuf row stride (fp16): 128x136

#define OFF_BGS  0                                  // 128 f32
#define OFF_BFC  512
#define OFF_SC   1024
#define OFF_SH   1536
#define OFF_SB   2048                               // B (8704)
#define OFF_TBUF (OFF_SB + 32 * SB_STR * 2)         // t (34816); phase-1 A overlays
#define OFF_SA   OFF_TBUF
#define SMEM_TOT (OFF_TBUF + 128 * TB_STR * 2)      // 45568 B

__global__ __launch_bounds__(256) void mma_layer_kernel(
    const __half* __restrict__ af,     // [3n][HD]
    const __half* __restrict__ wt,     // this layer: [4 slots][128][128]
    const float* __restrict__ bg,      // [3][HD]
    const float* __restrict__ bfc,
    const float* __restrict__ gamma, const float* __restrict__ beta,
    const float* __restrict__ mean,  const float* __restrict__ var,
    float* __restrict__ outf,          // fp32 output (layer 1) or null
    __half* __restrict__ outh,         // fp16 output (layer 0) or null
    int n)
{
    extern __shared__ char smem[];
    const uint32_t sb = smem_to_u32(smem);
    float* bgs  = (float*)(smem + OFF_BGS);
    float* bfcs = (float*)(smem + OFF_BFC);
    float* scs  = (float*)(smem + OFF_SC);
    float* shs  = (float*)(smem + OFF_SH);

    const int tid  = threadIdx.x;
    const int lane = tid & 31;
    const int wid  = tid >> 5;
    const int wm   = wid & 3;          // warp row  (m: 32 each)
    const int wn   = wid >> 2;         // warp col  (n: 64 each)
    const int bn0  = blockIdx.x * 128;

    if (tid < HD) {
        bgs[tid]  = __ldg(bg + tid) + __ldg(bg + HD + tid) + __ldg(bg + 2 * HD + tid);
        bfcs[tid] = __ldg(bfc + tid);
        float sc = __ldg(gamma + tid) * rsqrtf(__ldg(var + tid) + EPS);
        scs[tid] = sc;
        shs[tid] = __ldg(beta + tid) - __ldg(mean + tid) * sc;
    }

    const int lrow = lane & 15, lcol = lane >> 4;

    float acc[2][8][4];
    #pragma unroll
    for (int mi = 0; mi < 2; mi++)
        #pragma unroll
        for (int t = 0; t < 8; t++)
            #pragma unroll
            for (int q = 0; q < 4; q++) acc[mi][t][q] = 0.f;

    const int ar = tid >> 1, ahalf = tid & 1;        // A: 128 rows x 2 halves of 16
    const int br = tid >> 3, bc = tid & 7;           // B: 32 rows x 8 chunks of 16

    // ================= phase 1: 3 relations, K=128 each =======================
    for (int r = 0; r < 3; r++) {
        const __half* af_base = af + (size_t)r * n * HD;
        const __half* wp_base = wt + (size_t)r * 16384;
        for (int kc = 0; kc < 4; kc++) {
            __syncthreads();
            // stage A [128][32]
            {
                int gnode = bn0 + ar;
                uint4 v0 = {0,0,0,0}, v1 = {0,0,0,0};
                if (gnode < n) {
                    const uint4* ph = (const uint4*)(af_base + (size_t)gnode * HD + kc * 32 + ahalf * 16);
                    v0 = __ldg(ph); v1 = __ldg(ph + 1);
                }
                __half* dh = (__half*)(smem + OFF_SA) + ar * SA_STR + ahalf * 16;
                *(uint4*)dh = v0; *(uint4*)(dh + 8) = v1;
            }
            // stage B [32][128]
            {
                const uint4* ph = (const uint4*)(wp_base + (size_t)(kc * 32 + br) * HD + bc * 16);
                uint4 v0 = __ldg(ph), v1 = __ldg(ph + 1);
                __half* dh = (__half*)(smem + OFF_SB) + br * SB_STR + bc * 16;
                *(uint4*)dh = v0; *(uint4*)(dh + 8) = v1;
            }
            __syncthreads();

            #pragma unroll
            for (int kb = 0; kb < 32; kb += 16) {
                uint32_t ahf[2][4];
                #pragma unroll
                for (int mi = 0; mi < 2; mi++) {
                    uint32_t aoff = (uint32_t)((wm * 32 + mi * 16 + lrow) * SA_STR + kb + lcol * 8) * 2;
                    ldsm_x4(ahf[mi], sb + OFF_SA + aoff);
                }
                #pragma unroll
                for (int g = 0; g < 4; g++) {
                    uint32_t bh[4];
                    uint32_t boff = (uint32_t)((kb + lrow) * SB_STR + wn * 64 + g * 16 + lcol * 8) * 2;
                    ldsm_x4t(bh, sb + OFF_SB + boff);
                    #pragma unroll
                    for (int mi = 0; mi < 2; mi++) {
                        #pragma unroll
                        for (int nj = 0; nj < 2; nj++)
                            mma_f16(acc[mi][g * 2 + nj], ahf[mi], bh[nj * 2], bh[nj * 2 + 1]);
                    }
                }
            }
        }
    }

    // ================= transition: t = acc + bg -> tbuf (fp16) =================
    __syncthreads();
    {
        __half* th = (__half*)(smem + OFF_TBUF);
        #pragma unroll
        for (int mi = 0; mi < 2; mi++) {
            #pragma unroll
            for (int t = 0; t < 8; t++) {
                int g = t >> 1, nj = t & 1;
                int row0 = wm * 32 + mi * 16 + (lane >> 2);
                int col  = wn * 64 + g * 16 + nj * 8 + (lane & 3) * 2;
                float b0 = bgs[col], b1 = bgs[col + 1];
                #pragma unroll
                for (int half = 0; half < 2; half++) {
                    int row = row0 + half * 8;
                    __half2 hp = __floats2half2_rn(acc[mi][t][half * 2] + b0,
                                                   acc[mi][t][half * 2 + 1] + b1);
                    *(uint32_t*)(th + row * TB_STR + col) = *(uint32_t*)&hp;
                }
                #pragma unroll
                for (int q = 0; q < 4; q++) acc[mi][t][q] = 0.f;
            }
        }
    }

    // ================= phase 2: y = t @ Wfc =====================================
    {
        const __half* wp_base = wt + (size_t)3 * 16384;
        for (int kc = 0; kc < 4; kc++) {
            __syncthreads();
            {
                const uint4* ph = (const uint4*)(wp_base + (size_t)(kc * 32 + br) * HD + bc * 16);
                uint4 v0 = __ldg(ph), v1 = __ldg(ph + 1);
                __half* dh = (__half*)(smem + OFF_SB) + br * SB_STR + bc * 16;
                *(uint4*)dh = v0; *(uint4*)(dh + 8) = v1;
            }
            __syncthreads();

            #pragma unroll
            for (int kb2 = 0; kb2 < 32; kb2 += 16) {
                int kb = kc * 32 + kb2;
                uint32_t ahf[2][4];
                #pragma unroll
                for (int mi = 0; mi < 2; mi++) {
                    uint32_t aoff = (uint32_t)((wm * 32 + mi * 16 + lrow) * TB_STR + kb + lcol * 8) * 2;
                    ldsm_x4(ahf[mi], sb + OFF_TBUF + aoff);
                }
                #pragma unroll
                for (int g = 0; g < 4; g++) {
                    uint32_t bh[4];
                    uint32_t boff = (uint32_t)((kb2 + lrow) * SB_STR + wn * 64 + g * 16 + lcol * 8) * 2;
                    ldsm_x4t(bh, sb + OFF_SB + boff);
                    #pragma unroll
                    for (int mi = 0; mi < 2; mi++) {
                        #pragma unroll
                        for (int nj = 0; nj < 2; nj++)
                            mma_f16(acc[mi][g * 2 + nj], ahf[mi], bh[nj * 2], bh[nj * 2 + 1]);
                    }
                }
            }
        }
    }

    // ================= epilogue: ReLU + BN, store ==============================
    #pragma unroll
    for (int mi = 0; mi < 2; mi++) {
        #pragma unroll
        for (int t = 0; t < 8; t++) {
            int g = t >> 1, nj = t & 1;
            int row0 = wm * 32 + mi * 16 + (lane >> 2);
            int col  = wn * 64 + g * 16 + nj * 8 + (lane & 3) * 2;
            float bf0 = bfcs[col], bf1 = bfcs[col + 1];
            float sc0 = scs[col], sc1 = scs[col + 1];
            float sh0 = shs[col], sh1 = shs[col + 1];
            #pragma unroll
            for (int half = 0; half < 2; half++) {
                int node = bn0 + row0 + half * 8;
                if (node < n) {
                    float y0 = fmaxf(acc[mi][t][half * 2]     + bf0, 0.f);
                    float y1 = fmaxf(acc[mi][t][half * 2 + 1] + bf1, 0.f);
                    float v0 = y0 * sc0 + sh0;
                    float v1 = y1 * sc1 + sh1;
                    if (outh) {
                        __half2 hv = __floats2half2_rn(v0, v1);
                        *(uint32_t*)(outh + (size_t)node * HD + col) = *(uint32_t*)&hv;
                    } else {
                        *(float2*)(outf + (size_t)node * HD + col) = make_float2(v0, v1);
                    }
                }
            }
        }
    }
}

// ---------------- launch --------------------------------------------------------
extern "C" void kernel_launch(void* const* d_in, const int* in_sizes, int n_in,
                              void* d_out, int out_size)
{
    const float* x     = (const float*)d_in[0];
    const int* srcs[3] = {(const int*)d_in[1], (const int*)d_in[3], (const int*)d_in[5]};
    const int* dsts[3] = {(const int*)d_in[2], (const int*)d_in[4], (const int*)d_in[6]};
    const float* Wg0   = (const float*)d_in[7];
    const float* bg0   = (const float*)d_in[8];
    const float* Wg1   = (const float*)d_in[9];
    const float* bg1   = (const float*)d_in[10];
    const float* Wfc   = (const float*)d_in[11];
    const float* bfc   = (const float*)d_in[12];
    const float* gamma = (const float*)d_in[13];
    const float* beta  = (const float*)d_in[14];
    const float* mean  = (const float*)d_in[15];
    const float* var   = (const float*)d_in[16];

    int n = in_sizes[0] / HD;
    int es[3] = {in_sizes[1], in_sizes[3], in_sizes[5]};
    int emax = es[0] > es[1] ? es[0] : es[1];
    if (es[2] > emax) emax = es[2];

    int *p_deg, *p_off, *p_cur, *p_csum;
    int2* p_csr;
    __half *p_af, *p_wt, *p_xh, *p_h;
    cudaGetSymbolAddress((void**)&p_deg,  g_deg);
    cudaGetSymbolAddress((void**)&p_off,  g_off);
    cudaGetSymbolAddress((void**)&p_cur,  g_cur);
    cudaGetSymbolAddress((void**)&p_csum, g_csum);
    cudaGetSymbolAddress((void**)&p_csr,  g_csr);
    cudaGetSymbolAddress((void**)&p_af,   g_af);
    cudaGetSymbolAddress((void**)&p_wt,   g_wt);
    cudaGetSymbolAddress((void**)&p_xh,   g_xh);
    cudaGetSymbolAddress((void**)&p_h,    g_h);

    const int NT = 256;
    const int nchunks = (n + 255) / 256;

    cudaFuncSetAttribute(mma_layer_kernel, cudaFuncAttributeMaxDynamicSharedMemorySize, SMEM_TOT);

    // 0) fused util: zero deg, x->fp16, weight prep (1 launch)
    int c4 = n * HD / 4;
    int zb = (6 * n + 255) / 256;
    int xb = (c4 + 255) / 256;
    int ub = zb + xb + 512;
    prework_util_kernel<<<ub, 256>>>(p_deg, x, p_xh, Wg0, Wg1, Wfc, p_wt, n, c4, zb, xb);

    // 1) degrees (merged over relations); rsqrt folded into consumers
    {
        dim3 grid((emax + NT - 1) / NT, 3);
        count_pair3_kernel<<<grid, NT>>>(srcs[0], dsts[0], srcs[1], dsts[1], srcs[2], dsts[2],
                                         es[0], es[1], es[2], p_deg, n);
    }

    // 2) CSR by dst: node-scale stages merged (chunk_sum3 / scan3 / write_offsets3),
    //    edge-scale fill per relation
    {
        dim3 gc(nchunks, 3);
        chunk_sum3_kernel<<<gc, 256>>>(p_deg, p_csum, n);
        scan3_kernel<<<3, 512>>>(p_csum, nchunks);
        write_offsets3_kernel<<<gc, 256>>>(p_deg, p_csum, p_off, p_cur, n);
    }
    for (int r = 0; r < 3; r++) {
        csr_fill_kernel<<<(es[r] + NT - 1) / NT, NT>>>(
            srcs[r], dsts[r],
            p_deg + (size_t)2 * r * n,
            p_cur + (size_t)r * NMAX,
            p_csr + (size_t)r * EMAX, es[r]);
    }

    // 3) layers (per-relation gather launches — the proven form)
    int mblocks = (n + 127) / 128;
    for (int layer = 0; layer < 2; layer++) {
        const __half* hin = (layer == 0) ? p_xh : p_h;
        for (int r = 0; r < 3; r++) {
            long long thr = (long long)n * 32;
            int blocks = (int)((thr + NT - 1) / NT);
            gather_kernel<<<blocks, NT>>>(hin,
                                          p_csr + (size_t)r * EMAX,
                                          p_off + (size_t)r * (NMAX + 1),
                                          p_deg + (size_t)(2 * r + 1) * n,
                                          p_af + (size_t)r * n * HD, n);
        }
        mma_layer_kernel<<<mblocks, 256, SMEM_TOT>>>(
            p_af,
            p_wt + (size_t)layer * 4 * 16384,
            (layer == 0) ? bg0 : bg1,
            bfc + (size_t)layer * HD,
            gamma + (size_t)layer * HD, beta + (size_t)layer * HD,
            mean + (size_t)layer * HD, var + (size_t)layer * HD,
            (layer == 0) ? nullptr : (float*)d_out,
            (layer == 0) ? p_h : nullptr,
            n);
    }
}